// round 1
// baseline (speedup 1.0000x reference)
#include <cuda_runtime.h>
#include <math.h>

#define DIMC 384
#define NH 6
#define HD 64
#define MLPD 1536
#define BATCH 8
#define SEQ 1024
#define M_TOT (BATCH*SEQ)          // 8192
#define ATT_SCALE 0.125f           // 64^-0.5
#define LN_EPS 1e-5f

// ---- scratch (static device allocations are allowed) ----
__device__ float g_h[M_TOT * DIMC];        // LN output (reused for LN1 and LN2)
__device__ float g_qkv[M_TOT * 3 * DIMC];  // qkv projection
__device__ float g_ao[M_TOT * DIMC];       // attention output [B,N,H*D]
__device__ float g_x1[M_TOT * DIMC];       // x after attention residual
__device__ float g_m[M_TOT * MLPD];        // MLP hidden

// ============================================================
// LayerNorm: one block per row, 128 threads, 3 elems/thread
// ============================================================
__global__ __launch_bounds__(128)
void ln_kernel(const float* __restrict__ x, const float* __restrict__ w,
               const float* __restrict__ b, float* __restrict__ out) {
    int row = blockIdx.x;
    int tid = threadIdx.x;
    const float* xr = x + (size_t)row * DIMC;
    float v0 = xr[tid], v1 = xr[tid + 128], v2 = xr[tid + 256];

    __shared__ float red[4];
    float s = v0 + v1 + v2;
    #pragma unroll
    for (int o = 16; o > 0; o >>= 1) s += __shfl_down_sync(0xffffffff, s, o);
    if ((tid & 31) == 0) red[tid >> 5] = s;
    __syncthreads();
    float mean = (red[0] + red[1] + red[2] + red[3]) * (1.0f / DIMC);
    __syncthreads();

    float d0 = v0 - mean, d1 = v1 - mean, d2 = v2 - mean;
    float q = d0 * d0 + d1 * d1 + d2 * d2;
    #pragma unroll
    for (int o = 16; o > 0; o >>= 1) q += __shfl_down_sync(0xffffffff, q, o);
    if ((tid & 31) == 0) red[tid >> 5] = q;
    __syncthreads();
    float var = (red[0] + red[1] + red[2] + red[3]) * (1.0f / DIMC);
    float r = rsqrtf(var + LN_EPS);

    float* orow = out + (size_t)row * DIMC;
    orow[tid]       = d0 * r * w[tid]       + b[tid];
    orow[tid + 128] = d1 * r * w[tid + 128] + b[tid + 128];
    orow[tid + 256] = d2 * r * w[tid + 256] + b[tid + 256];
}

// ============================================================
// Tiled SGEMM: C[M,N] = A[M,K] @ W[N,K]^T (+ epilogue)
// EPI 0: none   EPI 1: +bias[c] +res[r,c]   EPI 2: +bias[c], exact GELU
// 64x64 tile, BK=16, 256 threads, 4x4 per thread
// ============================================================
template <int EPI>
__global__ __launch_bounds__(256)
void gemm_kernel(const float* __restrict__ A, const float* __restrict__ W,
                 const float* __restrict__ bias, const float* __restrict__ res,
                 float* __restrict__ C, int M, int N, int K) {
    __shared__ float As[16][68];  // As[k][m]
    __shared__ float Bs[16][68];  // Bs[k][n]
    int tid = threadIdx.x;
    int tx = tid & 15, ty = tid >> 4;
    int m0 = blockIdx.y * 64;
    int n0 = blockIdx.x * 64;

    int lr = tid >> 2;   // 0..63
    int lq = tid & 3;    // 0..3 (k-quad)
    const float* Aldg = A + (size_t)(m0 + lr) * K + lq * 4;
    const float* Wldg = W + (size_t)(n0 + lr) * K + lq * 4;

    float acc[4][4] = {};
    for (int k0 = 0; k0 < K; k0 += 16) {
        float4 av = *(const float4*)(Aldg + k0);
        float4 bv = *(const float4*)(Wldg + k0);
        __syncthreads();
        As[lq * 4 + 0][lr] = av.x; As[lq * 4 + 1][lr] = av.y;
        As[lq * 4 + 2][lr] = av.z; As[lq * 4 + 3][lr] = av.w;
        Bs[lq * 4 + 0][lr] = bv.x; Bs[lq * 4 + 1][lr] = bv.y;
        Bs[lq * 4 + 2][lr] = bv.z; Bs[lq * 4 + 3][lr] = bv.w;
        __syncthreads();
        #pragma unroll
        for (int k = 0; k < 16; k++) {
            float4 a4 = *(const float4*)&As[k][ty * 4];
            float4 b4 = *(const float4*)&Bs[k][tx * 4];
            float aa[4] = {a4.x, a4.y, a4.z, a4.w};
            float bb[4] = {b4.x, b4.y, b4.z, b4.w};
            #pragma unroll
            for (int i = 0; i < 4; i++)
                #pragma unroll
                for (int j = 0; j < 4; j++)
                    acc[i][j] = fmaf(aa[i], bb[j], acc[i][j]);
        }
    }

    #pragma unroll
    for (int i = 0; i < 4; i++) {
        int r = m0 + ty * 4 + i;
        int c = n0 + tx * 4;
        float4 o;
        float* oe = &o.x;
        #pragma unroll
        for (int j = 0; j < 4; j++) {
            float v = acc[i][j];
            if (EPI == 1) v += bias[c + j] + res[(size_t)r * N + c + j];
            if (EPI == 2) {
                v += bias[c + j];
                v = 0.5f * v * (1.0f + erff(v * 0.70710678118654752f));
            }
            oe[j] = v;
        }
        *(float4*)(C + (size_t)r * N + c) = o;
    }
}

// ============================================================
// L2Q attention, streaming over key tiles.
// grid: (SEQ/64, B*H), block 256.
// smem (dynamic): qsT[64][68] | kfT[64][68] (K^T then F^T) | vs[64][68]
// ============================================================
__global__ __launch_bounds__(256)
void attn_kernel(const float* __restrict__ qkv,
                 const float* __restrict__ alpha, const float* __restrict__ beta,
                 const float* __restrict__ gamma, float* __restrict__ ao) {
    extern __shared__ float sm[];
    float* qsT = sm;                 // qsT[d][row]
    float* kfT = sm + 64 * 68;       // ksT[d][key] -> later FsT[key][row]
    float* vs  = sm + 2 * 64 * 68;   // vs[key][d]

    int tid = threadIdx.x;
    int tx = tid & 15, ty = tid >> 4;
    int bh = blockIdx.y;
    int b = bh / NH, h = bh % NH;
    int r0 = blockIdx.x * 64;
    float al = alpha[h], be = beta[h], ga = gamma[h];

    const float* qbase = qkv + (size_t)b * SEQ * (3 * DIMC) + h * HD;
    const float* kbase = qbase + DIMC;
    const float* vbase = qbase + 2 * DIMC;

    // load Q tile transposed
    {
        int row = tid >> 2;
        #pragma unroll
        for (int r = 0; r < 4; r++) {
            int dq = (tid & 3) * 4 + r;     // 0..15
            float4 v4 = *(const float4*)(qbase + (size_t)(r0 + row) * (3 * DIMC) + dq * 4);
            qsT[(dq * 4 + 0) * 68 + row] = v4.x;
            qsT[(dq * 4 + 1) * 68 + row] = v4.y;
            qsT[(dq * 4 + 2) * 68 + row] = v4.z;
            qsT[(dq * 4 + 3) * 68 + row] = v4.w;
        }
    }

    float oacc[4][4] = {};
    float den[4] = {};

    for (int t = 0; t < SEQ / 64; t++) {
        int kk0 = t * 64;
        __syncthreads();
        // load K^T (into kfT) and V tiles
        {
            int key = tid >> 2;
            #pragma unroll
            for (int r = 0; r < 4; r++) {
                int dq = (tid & 3) * 4 + r;
                float4 k4 = *(const float4*)(kbase + (size_t)(kk0 + key) * (3 * DIMC) + dq * 4);
                kfT[(dq * 4 + 0) * 68 + key] = k4.x;
                kfT[(dq * 4 + 1) * 68 + key] = k4.y;
                kfT[(dq * 4 + 2) * 68 + key] = k4.z;
                kfT[(dq * 4 + 3) * 68 + key] = k4.w;
                float4 v4 = *(const float4*)(vbase + (size_t)(kk0 + key) * (3 * DIMC) + dq * 4);
                *(float4*)&vs[key * 68 + dq * 4] = v4;
            }
        }
        __syncthreads();

        // S = Q K^T
        float sacc[4][4] = {};
        #pragma unroll 8
        for (int d = 0; d < 64; d++) {
            float4 a4 = *(const float4*)&qsT[d * 68 + ty * 4];
            float4 b4 = *(const float4*)&kfT[d * 68 + tx * 4];
            float aa[4] = {a4.x, a4.y, a4.z, a4.w};
            float bb[4] = {b4.x, b4.y, b4.z, b4.w};
            #pragma unroll
            for (int i = 0; i < 4; i++)
                #pragma unroll
                for (int j = 0; j < 4; j++)
                    sacc[i][j] = fmaf(aa[i], bb[j], sacc[i][j]);
        }
        __syncthreads();   // everyone done reading K^T from kfT

        // f = relu(quadratic), write F^T into kfT, accumulate row denominators
        #pragma unroll
        for (int i = 0; i < 4; i++)
            #pragma unroll
            for (int j = 0; j < 4; j++) {
                float s = sacc[i][j] * ATT_SCALE;
                float f = fmaxf(fmaf(al * s, s, fmaf(be, s, ga)), 0.0f);
                den[i] += f;
                kfT[(tx * 4 + j) * 68 + ty * 4 + i] = f;
            }
        __syncthreads();

        // O += F V
        #pragma unroll 8
        for (int j = 0; j < 64; j++) {
            float4 a4 = *(const float4*)&kfT[j * 68 + ty * 4];
            float4 b4 = *(const float4*)&vs[j * 68 + tx * 4];
            float aa[4] = {a4.x, a4.y, a4.z, a4.w};
            float bb[4] = {b4.x, b4.y, b4.z, b4.w};
            #pragma unroll
            for (int i = 0; i < 4; i++)
                #pragma unroll
                for (int jj = 0; jj < 4; jj++)
                    oacc[i][jj] = fmaf(aa[i], bb[jj], oacc[i][jj]);
        }
    }

    // reduce den across the 16 tx threads per row
    __syncthreads();
    #pragma unroll
    for (int i = 0; i < 4; i++) vs[(ty * 4 + i) * 17 + tx] = den[i];
    __syncthreads();
    if (tid < 64) {
        float s = 0.0f;
        #pragma unroll
        for (int j = 0; j < 16; j++) s += vs[tid * 17 + j];
        qsT[tid] = s;    // reduced denominator per row
    }
    __syncthreads();

    #pragma unroll
    for (int i = 0; i < 4; i++) {
        int row = ty * 4 + i;
        float dinv = 1.0f / (qsT[row] + 1e-6f);
        float4 o;
        o.x = oacc[i][0] * dinv; o.y = oacc[i][1] * dinv;
        o.z = oacc[i][2] * dinv; o.w = oacc[i][3] * dinv;
        *(float4*)(ao + (size_t)(b * SEQ + r0 + row) * DIMC + h * HD + tx * 4) = o;
    }
}

// ============================================================
// launch
// ============================================================
extern "C" void kernel_launch(void* const* d_in, const int* in_sizes, int n_in,
                              void* d_out, int out_size) {
    const float* x      = (const float*)d_in[0];
    const float* qkv_w  = (const float*)d_in[1];
    const float* proj_w = (const float*)d_in[2];
    const float* proj_b = (const float*)d_in[3];
    const float* alpha  = (const float*)d_in[4];
    const float* beta   = (const float*)d_in[5];
    const float* gamma  = (const float*)d_in[6];
    const float* ln1_w  = (const float*)d_in[7];
    const float* ln1_b  = (const float*)d_in[8];
    const float* ln2_w  = (const float*)d_in[9];
    const float* ln2_b  = (const float*)d_in[10];
    const float* w1     = (const float*)d_in[11];
    const float* b1     = (const float*)d_in[12];
    const float* w2     = (const float*)d_in[13];
    const float* b2     = (const float*)d_in[14];
    float* out = (float*)d_out;

    float *h, *qkv, *ao, *x1, *m;
    cudaGetSymbolAddress((void**)&h,   g_h);
    cudaGetSymbolAddress((void**)&qkv, g_qkv);
    cudaGetSymbolAddress((void**)&ao,  g_ao);
    cudaGetSymbolAddress((void**)&x1,  g_x1);
    cudaGetSymbolAddress((void**)&m,   g_m);

    cudaFuncSetAttribute(attn_kernel, cudaFuncAttributeMaxDynamicSharedMemorySize,
                         3 * 64 * 68 * 4);

    // 1. LN1
    ln_kernel<<<M_TOT, 128>>>(x, ln1_w, ln1_b, h);
    // 2. QKV projection: [8192,384] x [1152,384]^T
    gemm_kernel<0><<<dim3(3 * DIMC / 64, M_TOT / 64), 256>>>(h, qkv_w, nullptr, nullptr,
                                                             qkv, M_TOT, 3 * DIMC, DIMC);
    // 3. L2Q attention
    attn_kernel<<<dim3(SEQ / 64, BATCH * NH), 256, 3 * 64 * 68 * 4>>>(qkv, alpha, beta, gamma, ao);
    // 4. proj + bias + residual
    gemm_kernel<1><<<dim3(DIMC / 64, M_TOT / 64), 256>>>(ao, proj_w, proj_b, x,
                                                         x1, M_TOT, DIMC, DIMC);
    // 5. LN2
    ln_kernel<<<M_TOT, 128>>>(x1, ln2_w, ln2_b, h);
    // 6. MLP fc1 + bias + GELU
    gemm_kernel<2><<<dim3(MLPD / 64, M_TOT / 64), 256>>>(h, w1, b1, nullptr,
                                                         m, M_TOT, MLPD, DIMC);
    // 7. MLP fc2 + bias + residual
    gemm_kernel<1><<<dim3(DIMC / 64, M_TOT / 64), 256>>>(m, w2, b2, x1,
                                                         out, M_TOT, DIMC, MLPD);
}

// round 2
// speedup vs baseline: 2.1900x; 2.1900x over previous
#include <cuda_runtime.h>
#include <math.h>
#include <stdint.h>

#define DIMC 384
#define NH 6
#define HD 64
#define MLPD 1536
#define BATCH 8
#define SEQ 1024
#define M_TOT (BATCH*SEQ)
#define ATT_SCALE 0.125f
#define LN_EPS 1e-5f

__device__ float g_h[M_TOT * DIMC];
__device__ float g_qkv[M_TOT * 3 * DIMC];
__device__ float g_ao[M_TOT * DIMC];
__device__ float g_x1[M_TOT * DIMC];
__device__ float g_m[M_TOT * MLPD];

__device__ __forceinline__ float tf32r(float x) {
    float y; asm("cvt.rna.tf32.f32 %0, %1;" : "=f"(y) : "f"(x)); return y;
}

__device__ __forceinline__ void mma_tf32(float c[4], uint32_t a0, uint32_t a1,
                                         uint32_t a2, uint32_t a3,
                                         uint32_t b0, uint32_t b1) {
    asm volatile(
        "mma.sync.aligned.m16n8k8.row.col.f32.tf32.tf32.f32 "
        "{%0,%1,%2,%3},{%4,%5,%6,%7},{%8,%9},{%0,%1,%2,%3};\n"
        : "+f"(c[0]), "+f"(c[1]), "+f"(c[2]), "+f"(c[3])
        : "r"(a0), "r"(a1), "r"(a2), "r"(a3), "r"(b0), "r"(b1));
}

// ============================================================
// LayerNorm
// ============================================================
__global__ __launch_bounds__(128)
void ln_kernel(const float* __restrict__ x, const float* __restrict__ w,
               const float* __restrict__ b, float* __restrict__ out) {
    int row = blockIdx.x;
    int tid = threadIdx.x;
    const float* xr = x + (size_t)row * DIMC;
    float v0 = xr[tid], v1 = xr[tid + 128], v2 = xr[tid + 256];

    __shared__ float red[4];
    float s = v0 + v1 + v2;
    #pragma unroll
    for (int o = 16; o > 0; o >>= 1) s += __shfl_down_sync(0xffffffff, s, o);
    if ((tid & 31) == 0) red[tid >> 5] = s;
    __syncthreads();
    float mean = (red[0] + red[1] + red[2] + red[3]) * (1.0f / DIMC);
    __syncthreads();

    float d0 = v0 - mean, d1 = v1 - mean, d2 = v2 - mean;
    float q = d0 * d0 + d1 * d1 + d2 * d2;
    #pragma unroll
    for (int o = 16; o > 0; o >>= 1) q += __shfl_down_sync(0xffffffff, q, o);
    if ((tid & 31) == 0) red[tid >> 5] = q;
    __syncthreads();
    float var = (red[0] + red[1] + red[2] + red[3]) * (1.0f / DIMC);
    float r = rsqrtf(var + LN_EPS);

    float* orow = out + (size_t)row * DIMC;
    orow[tid]       = d0 * r * w[tid]       + b[tid];
    orow[tid + 128] = d1 * r * w[tid + 128] + b[tid + 128];
    orow[tid + 256] = d2 * r * w[tid + 256] + b[tid + 256];
}

// ============================================================
// TF32 tensor-core GEMM: C[M,N] = A[M,K] @ W[N,K]^T (+ epilogue)
// 128x128 tile, BK=16, 256 threads, warps 2x4 (64x32 warp tiles)
// EPI 0: none   EPI 1: +bias +res   EPI 2: +bias, exact GELU
// ============================================================
template <int EPI>
__global__ __launch_bounds__(256)
void gemm_tc(const float* __restrict__ A, const float* __restrict__ W,
             const float* __restrict__ bias, const float* __restrict__ res,
             float* __restrict__ C, int M, int N, int K) {
    __shared__ float As[2][128][20];
    __shared__ float Bs[2][128][20];
    int tid = threadIdx.x;
    int lane = tid & 31, wid = tid >> 5;
    int wm = wid >> 2, wn = wid & 3;
    int m0 = blockIdx.y * 128, n0 = blockIdx.x * 128;

    int lr = tid >> 2;
    int lc = (tid & 3) * 4;
    const float* Ap = A + (size_t)(m0 + lr) * K + lc;
    const float* Wp = W + (size_t)(n0 + lr) * K + lc;

    float acc[4][4][4];
    #pragma unroll
    for (int i = 0; i < 4; i++)
        #pragma unroll
        for (int j = 0; j < 4; j++)
            #pragma unroll
            for (int r = 0; r < 4; r++) acc[i][j][r] = 0.f;

    int T = K / 16;
    float4 av0, av1, bv0, bv1;
    av0 = *(const float4*)(Ap);
    av1 = *(const float4*)(Ap + (size_t)64 * K);
    bv0 = *(const float4*)(Wp);
    bv1 = *(const float4*)(Wp + (size_t)64 * K);
    // store stage 0
    As[0][lr][lc + 0] = tf32r(av0.x); As[0][lr][lc + 1] = tf32r(av0.y);
    As[0][lr][lc + 2] = tf32r(av0.z); As[0][lr][lc + 3] = tf32r(av0.w);
    As[0][lr + 64][lc + 0] = tf32r(av1.x); As[0][lr + 64][lc + 1] = tf32r(av1.y);
    As[0][lr + 64][lc + 2] = tf32r(av1.z); As[0][lr + 64][lc + 3] = tf32r(av1.w);
    Bs[0][lr][lc + 0] = tf32r(bv0.x); Bs[0][lr][lc + 1] = tf32r(bv0.y);
    Bs[0][lr][lc + 2] = tf32r(bv0.z); Bs[0][lr][lc + 3] = tf32r(bv0.w);
    Bs[0][lr + 64][lc + 0] = tf32r(bv1.x); Bs[0][lr + 64][lc + 1] = tf32r(bv1.y);
    Bs[0][lr + 64][lc + 2] = tf32r(bv1.z); Bs[0][lr + 64][lc + 3] = tf32r(bv1.w);
    __syncthreads();

    for (int t = 0; t < T; t++) {
        int s = t & 1;
        if (t + 1 < T) {
            const float* Ap2 = Ap + (t + 1) * 16;
            const float* Wp2 = Wp + (t + 1) * 16;
            av0 = *(const float4*)(Ap2);
            av1 = *(const float4*)(Ap2 + (size_t)64 * K);
            bv0 = *(const float4*)(Wp2);
            bv1 = *(const float4*)(Wp2 + (size_t)64 * K);
        }
        #pragma unroll
        for (int kk = 0; kk < 16; kk += 8) {
            int ac = kk + (lane & 3);
            uint32_t af[4][4];
            #pragma unroll
            for (int mi = 0; mi < 4; mi++) {
                int mr = wm * 64 + mi * 16 + (lane >> 2);
                af[mi][0] = __float_as_uint(As[s][mr][ac]);
                af[mi][1] = __float_as_uint(As[s][mr + 8][ac]);
                af[mi][2] = __float_as_uint(As[s][mr][ac + 4]);
                af[mi][3] = __float_as_uint(As[s][mr + 8][ac + 4]);
            }
            #pragma unroll
            for (int ni = 0; ni < 4; ni++) {
                int nr = wn * 32 + ni * 8 + (lane >> 2);
                uint32_t b0 = __float_as_uint(Bs[s][nr][ac]);
                uint32_t b1 = __float_as_uint(Bs[s][nr][ac + 4]);
                #pragma unroll
                for (int mi = 0; mi < 4; mi++)
                    mma_tf32(acc[mi][ni], af[mi][0], af[mi][1], af[mi][2], af[mi][3], b0, b1);
            }
        }
        if (t + 1 < T) {
            int s2 = s ^ 1;
            As[s2][lr][lc + 0] = tf32r(av0.x); As[s2][lr][lc + 1] = tf32r(av0.y);
            As[s2][lr][lc + 2] = tf32r(av0.z); As[s2][lr][lc + 3] = tf32r(av0.w);
            As[s2][lr + 64][lc + 0] = tf32r(av1.x); As[s2][lr + 64][lc + 1] = tf32r(av1.y);
            As[s2][lr + 64][lc + 2] = tf32r(av1.z); As[s2][lr + 64][lc + 3] = tf32r(av1.w);
            Bs[s2][lr][lc + 0] = tf32r(bv0.x); Bs[s2][lr][lc + 1] = tf32r(bv0.y);
            Bs[s2][lr][lc + 2] = tf32r(bv0.z); Bs[s2][lr][lc + 3] = tf32r(bv0.w);
            Bs[s2][lr + 64][lc + 0] = tf32r(bv1.x); Bs[s2][lr + 64][lc + 1] = tf32r(bv1.y);
            Bs[s2][lr + 64][lc + 2] = tf32r(bv1.z); Bs[s2][lr + 64][lc + 3] = tf32r(bv1.w);
            __syncthreads();
        }
    }

    #pragma unroll
    for (int mi = 0; mi < 4; mi++) {
        int r = m0 + wm * 64 + mi * 16 + (lane >> 2);
        #pragma unroll
        for (int ni = 0; ni < 4; ni++) {
            int c = n0 + wn * 32 + ni * 8 + 2 * (lane & 3);
            float v[4] = {acc[mi][ni][0], acc[mi][ni][1], acc[mi][ni][2], acc[mi][ni][3]};
            int rr[2] = {r, r + 8};
            #pragma unroll
            for (int half = 0; half < 2; half++) {
                float x0 = v[half * 2 + 0], x1 = v[half * 2 + 1];
                if (EPI == 1) {
                    x0 += bias[c] + res[(size_t)rr[half] * N + c];
                    x1 += bias[c + 1] + res[(size_t)rr[half] * N + c + 1];
                }
                if (EPI == 2) {
                    x0 += bias[c];
                    x1 += bias[c + 1];
                    x0 = 0.5f * x0 * (1.0f + erff(x0 * 0.70710678118654752f));
                    x1 = 0.5f * x1 * (1.0f + erff(x1 * 0.70710678118654752f));
                }
                float2 o = {x0, x1};
                *(float2*)(C + (size_t)rr[half] * N + c) = o;
            }
        }
    }
}

// ============================================================
// L2Q attention with tf32 mma, streaming key tiles.
// grid (SEQ/64, B*H), 128 threads (4 warps; warp w owns q-rows w*16..+15)
// smem: Qs[64][68] | KFs[64][68] (K then F) | Vs[64][68]
// ============================================================
__global__ __launch_bounds__(128)
void attn_tc(const float* __restrict__ qkv,
             const float* __restrict__ alpha, const float* __restrict__ beta,
             const float* __restrict__ gamma, float* __restrict__ ao) {
    extern __shared__ float sm[];
    float (*Qs)[68]  = (float(*)[68])sm;
    float (*KFs)[68] = (float(*)[68])(sm + 64 * 68);
    float (*Vs)[68]  = (float(*)[68])(sm + 2 * 64 * 68);

    int tid = threadIdx.x, lane = tid & 31, wid = tid >> 5;
    int bh = blockIdx.y;
    int b = bh / NH, h = bh % NH;
    int r0 = blockIdx.x * 64;
    float al = alpha[h], be = beta[h], ga = gamma[h];

    const float* qbase = qkv + (size_t)b * SEQ * (3 * DIMC) + h * HD;
    const float* kbase = qbase + DIMC;
    const float* vbase = qbase + 2 * DIMC;

    // load Q tile (64x64), tf32-rounded
    int qr = tid >> 1, qh = (tid & 1) * 32;
    {
        const float* qp = qbase + (size_t)(r0 + qr) * (3 * DIMC) + qh;
        #pragma unroll
        for (int i = 0; i < 8; i++) {
            float4 v = *(const float4*)(qp + i * 4);
            Qs[qr][qh + i * 4 + 0] = tf32r(v.x);
            Qs[qr][qh + i * 4 + 1] = tf32r(v.y);
            Qs[qr][qh + i * 4 + 2] = tf32r(v.z);
            Qs[qr][qh + i * 4 + 3] = tf32r(v.w);
        }
    }

    float oacc[8][4];
    #pragma unroll
    for (int i = 0; i < 8; i++)
        #pragma unroll
        for (int j = 0; j < 4; j++) oacc[i][j] = 0.f;
    float den0 = 0.f, den1 = 0.f;

    int row0 = wid * 16 + (lane >> 2);

    for (int t = 0; t < SEQ / 64; t++) {
        int kk0 = t * 64;
        __syncthreads();   // prior reads of KFs/Vs complete
        {
            const float* kp = kbase + (size_t)(kk0 + qr) * (3 * DIMC) + qh;
            const float* vp = vbase + (size_t)(kk0 + qr) * (3 * DIMC) + qh;
            #pragma unroll
            for (int i = 0; i < 8; i++) {
                float4 kv = *(const float4*)(kp + i * 4);
                KFs[qr][qh + i * 4 + 0] = tf32r(kv.x);
                KFs[qr][qh + i * 4 + 1] = tf32r(kv.y);
                KFs[qr][qh + i * 4 + 2] = tf32r(kv.z);
                KFs[qr][qh + i * 4 + 3] = tf32r(kv.w);
                float4 vv = *(const float4*)(vp + i * 4);
                Vs[qr][qh + i * 4 + 0] = tf32r(vv.x);
                Vs[qr][qh + i * 4 + 1] = tf32r(vv.y);
                Vs[qr][qh + i * 4 + 2] = tf32r(vv.z);
                Vs[qr][qh + i * 4 + 3] = tf32r(vv.w);
            }
        }
        __syncthreads();

        // S = Q K^T  (per warp: 16 rows x 64 keys)
        float sacc[8][4];
        #pragma unroll
        for (int i = 0; i < 8; i++)
            #pragma unroll
            for (int j = 0; j < 4; j++) sacc[i][j] = 0.f;

        #pragma unroll
        for (int kk = 0; kk < 64; kk += 8) {
            int ac = kk + (lane & 3);
            uint32_t a0 = __float_as_uint(Qs[row0][ac]);
            uint32_t a1 = __float_as_uint(Qs[row0 + 8][ac]);
            uint32_t a2 = __float_as_uint(Qs[row0][ac + 4]);
            uint32_t a3 = __float_as_uint(Qs[row0 + 8][ac + 4]);
            #pragma unroll
            for (int ni = 0; ni < 8; ni++) {
                int br = ni * 8 + (lane >> 2);
                uint32_t b0 = __float_as_uint(KFs[br][ac]);
                uint32_t b1 = __float_as_uint(KFs[br][ac + 4]);
                mma_tf32(sacc[ni], a0, a1, a2, a3, b0, b1);
            }
        }
        __syncthreads();   // all warps done reading K

        // f = relu(alpha*s^2 + beta*s + gamma); write F into KFs
        #pragma unroll
        for (int ni = 0; ni < 8; ni++) {
            int cc = ni * 8 + 2 * (lane & 3);
            float s0 = sacc[ni][0] * ATT_SCALE;
            float s1 = sacc[ni][1] * ATT_SCALE;
            float s2 = sacc[ni][2] * ATT_SCALE;
            float s3 = sacc[ni][3] * ATT_SCALE;
            float f0 = fmaxf(fmaf(al * s0, s0, fmaf(be, s0, ga)), 0.f);
            float f1 = fmaxf(fmaf(al * s1, s1, fmaf(be, s1, ga)), 0.f);
            float f2 = fmaxf(fmaf(al * s2, s2, fmaf(be, s2, ga)), 0.f);
            float f3 = fmaxf(fmaf(al * s3, s3, fmaf(be, s3, ga)), 0.f);
            den0 += f0 + f1;
            den1 += f2 + f3;
            KFs[row0][cc] = tf32r(f0);     KFs[row0][cc + 1] = tf32r(f1);
            KFs[row0 + 8][cc] = tf32r(f2); KFs[row0 + 8][cc + 1] = tf32r(f3);
        }
        __syncthreads();

        // O += F V
        #pragma unroll
        for (int kk = 0; kk < 64; kk += 8) {
            int ac = kk + (lane & 3);
            uint32_t a0 = __float_as_uint(KFs[row0][ac]);
            uint32_t a1 = __float_as_uint(KFs[row0 + 8][ac]);
            uint32_t a2 = __float_as_uint(KFs[row0][ac + 4]);
            uint32_t a3 = __float_as_uint(KFs[row0 + 8][ac + 4]);
            #pragma unroll
            for (int ni = 0; ni < 8; ni++) {
                int nc = ni * 8 + (lane >> 2);
                uint32_t b0 = __float_as_uint(Vs[kk + (lane & 3)][nc]);
                uint32_t b1 = __float_as_uint(Vs[kk + (lane & 3) + 4][nc]);
                mma_tf32(oacc[ni], a0, a1, a2, a3, b0, b1);
            }
        }
    }

    // reduce denominators across the 4 lanes sharing each row
    den0 += __shfl_xor_sync(0xffffffff, den0, 1);
    den0 += __shfl_xor_sync(0xffffffff, den0, 2);
    den1 += __shfl_xor_sync(0xffffffff, den1, 1);
    den1 += __shfl_xor_sync(0xffffffff, den1, 2);
    float di0 = 1.0f / (den0 + 1e-6f);
    float di1 = 1.0f / (den1 + 1e-6f);

    float* aob = ao + (size_t)(b * SEQ + r0) * DIMC + h * HD;
    #pragma unroll
    for (int ni = 0; ni < 8; ni++) {
        int cc = ni * 8 + 2 * (lane & 3);
        float2 o0 = {oacc[ni][0] * di0, oacc[ni][1] * di0};
        float2 o1 = {oacc[ni][2] * di1, oacc[ni][3] * di1};
        *(float2*)(aob + (size_t)row0 * DIMC + cc) = o0;
        *(float2*)(aob + (size_t)(row0 + 8) * DIMC + cc) = o1;
    }
}

// ============================================================
// launch
// ============================================================
extern "C" void kernel_launch(void* const* d_in, const int* in_sizes, int n_in,
                              void* d_out, int out_size) {
    const float* x      = (const float*)d_in[0];
    const float* qkv_w  = (const float*)d_in[1];
    const float* proj_w = (const float*)d_in[2];
    const float* proj_b = (const float*)d_in[3];
    const float* alpha  = (const float*)d_in[4];
    const float* beta   = (const float*)d_in[5];
    const float* gamma  = (const float*)d_in[6];
    const float* ln1_w  = (const float*)d_in[7];
    const float* ln1_b  = (const float*)d_in[8];
    const float* ln2_w  = (const float*)d_in[9];
    const float* ln2_b  = (const float*)d_in[10];
    const float* w1     = (const float*)d_in[11];
    const float* b1     = (const float*)d_in[12];
    const float* w2     = (const float*)d_in[13];
    const float* b2     = (const float*)d_in[14];
    float* out = (float*)d_out;

    float *h, *qkv, *ao, *x1, *m;
    cudaGetSymbolAddress((void**)&h,   g_h);
    cudaGetSymbolAddress((void**)&qkv, g_qkv);
    cudaGetSymbolAddress((void**)&ao,  g_ao);
    cudaGetSymbolAddress((void**)&x1,  g_x1);
    cudaGetSymbolAddress((void**)&m,   g_m);

    cudaFuncSetAttribute(attn_tc, cudaFuncAttributeMaxDynamicSharedMemorySize,
                         3 * 64 * 68 * 4);

    ln_kernel<<<M_TOT, 128>>>(x, ln1_w, ln1_b, h);
    gemm_tc<0><<<dim3(3 * DIMC / 128, M_TOT / 128), 256>>>(h, qkv_w, nullptr, nullptr,
                                                           qkv, M_TOT, 3 * DIMC, DIMC);
    attn_tc<<<dim3(SEQ / 64, BATCH * NH), 128, 3 * 64 * 68 * 4>>>(qkv, alpha, beta, gamma, ao);
    gemm_tc<1><<<dim3(DIMC / 128, M_TOT / 128), 256>>>(ao, proj_w, proj_b, x,
                                                       x1, M_TOT, DIMC, DIMC);
    ln_kernel<<<M_TOT, 128>>>(x1, ln2_w, ln2_b, h);
    gemm_tc<2><<<dim3(MLPD / 128, M_TOT / 128), 256>>>(h, w1, b1, nullptr,
                                                       m, M_TOT, MLPD, DIMC);
    gemm_tc<1><<<dim3(DIMC / 128, M_TOT / 128), 256>>>(m, w2, b2, x1,
                                                       out, M_TOT, DIMC, MLPD);
}